// round 5
// baseline (speedup 1.0000x reference)
#include <cuda_runtime.h>
#include <cuda_fp16.h>

#define B_     2
#define N_IN_  262144
#define D_     32
#define N_OUT_ 65536
#define K_     4
#define NK_    9
#define TOTAL_ (B_ * N_OUT_ * K_)     // 524288 outputs
#define HALF_  (N_OUT_ * K_)          // 262144 outputs per batch

#define PROJ_BLOCKS_ 8192   // 65536 warps * 4 outputs = 262144 outputs (one batch)
#define PREP_BLOCKS_ 4096   // 1,048,576 threads: 8 floats each = one batch of x

// sigma-dedup results + interleaved coords + fp16 feature copy
__device__ float  g_uc0;                    // 1/(2*sigma^2) when uniform
__device__ int    g_u;                      // 1 = uniform sigma, 2 = general
__device__ float2 g_c2[B_ * N_IN_];         // (cx, cy) per input point
__device__ __half g_xh[B_ * N_IN_ * D_];    // fp16 features, 64B rows

// ---------- prep for one batch (device-side, role-block) ----------
__device__ __forceinline__ void prep_block(
    int pbid, int prep_batch,
    const float* __restrict__ x,
    const float* __restrict__ sigma,
    const float* __restrict__ cin)
{
    const int tid = pbid * 256 + (int)threadIdx.x;

    if (prep_batch == 0 && pbid == 0 && threadIdx.x < 32) {
        float s = sigma[threadIdx.x];
        float c = 1.0f / (2.0f * s * s);
        float c0 = __shfl_sync(0xffffffffu, c, 0);
        unsigned same = __ballot_sync(0xffffffffu, c == c0);
        if (threadIdx.x == 0) {
            g_u   = (same == 0xffffffffu) ? 1 : 2;
            g_uc0 = c0;
        }
    }

    // fp16 repack for this batch: 8 floats -> 8 halves per thread
    {
        const float4* x4 = (const float4*)(x + (size_t)prep_batch * N_IN_ * D_);
        float4 a = __ldg(&x4[tid * 2]);
        float4 bq = __ldg(&x4[tid * 2 + 1]);
        __half2 h0 = __floats2half2_rn(a.x, a.y);
        __half2 h1 = __floats2half2_rn(a.z, a.w);
        __half2 h2 = __floats2half2_rn(bq.x, bq.y);
        __half2 h3 = __floats2half2_rn(bq.z, bq.w);
        uint4 p;
        p.x = *(const unsigned*)&h0;
        p.y = *(const unsigned*)&h1;
        p.z = *(const unsigned*)&h2;
        p.w = *(const unsigned*)&h3;
        ((uint4*)(g_xh + (size_t)prep_batch * N_IN_ * D_))[tid] = p;
    }

    // coord pack for this batch: first 65536 threads, 4 points each
    if (tid < N_IN_ / 4) {
        float4 cx = __ldg(&((const float4*)(cin + prep_batch * N_IN_))[tid]);
        float4 cy = __ldg(&((const float4*)(cin + B_ * N_IN_ + prep_batch * N_IN_))[tid]);
        float4* dst = (float4*)(g_c2 + prep_batch * N_IN_);
        dst[tid * 2 + 0] = make_float4(cx.x, cy.x, cx.y, cy.y);
        dst[tid * 2 + 1] = make_float4(cx.z, cy.z, cx.w, cy.w);
    }
}

// ---------- proj for one batch (device-side, role-block) ----------
// Warp = 4 outputs. lane: g = lane>>3 (output), sl = lane&7 (channels 4sl..4sl+3).
__device__ __forceinline__ void proj_block(
    int pbid, int b,
    const float* __restrict__ cout,
    const float* __restrict__ sigma,
    const int*   __restrict__ nidx,
    float* __restrict__ out)
{
    const unsigned lane = threadIdx.x & 31u;
    const int w    = pbid * 8 + (int)(threadIdx.x >> 5);
    const int bnk0 = b * HALF_ + w * 4;
    const int g    = (int)(lane >> 3);
    const int sl   = (int)(lane & 7u);
    const int bnk  = bnk0 + g;

    int   idxA = 0, idxB = 0;
    float tA = 0.0f, tB = 0.0f;
    if (lane < 2 * NK_) {
        const int o = (lane >= NK_) ? 1 : 0;
        const int j = (int)lane - o * NK_;

        const int oA = bnk0 + o;
        idxA = __ldg(&nidx[(size_t)oA * NK_ + j]);
        const int oB = bnk0 + 2 + o;
        idxB = __ldg(&nidx[(size_t)oB * NK_ + j]);

        float2 cA = g_c2[b * N_IN_ + idxA];
        float2 cB = g_c2[b * N_IN_ + idxB];
        float oxA = __ldg(&cout[oA]);
        float oyA = __ldg(&cout[oA + TOTAL_]);
        float oxB = __ldg(&cout[oB]);
        float oyB = __ldg(&cout[oB + TOTAL_]);

        float dxA = oxA - cA.x, dyA = oyA - cA.y;
        float dxB = oxB - cB.x, dyB = oyB - cB.y;
        tA = -(dxA * dxA + dyA * dyA);
        tB = -(dxB * dxB + dyB * dyB);
    }

    const int selbase = (g & 1) * NK_;
    int ij[NK_];
#pragma unroll
    for (int j = 0; j < NK_; j++) {
        int a  = __shfl_sync(0xffffffffu, idxA, selbase + j);
        int bb = __shfl_sync(0xffffffffu, idxB, selbase + j);
        ij[j] = (g < 2) ? a : bb;
    }

    const uint2* xb = (const uint2*)g_xh + (size_t)b * N_IN_ * (D_ / 4) + sl;
    uint2 f[NK_];
#pragma unroll
    for (int j = 0; j < NK_; j++) f[j] = __ldg(xb + (size_t)ij[j] * (D_ / 4));

    float4 num = make_float4(0.f, 0.f, 0.f, 0.f);

    if (g_u == 1) {
        float eA = __expf(tA * g_uc0);
        float eB = __expf(tB * g_uc0);
        float den = 1e-9f;
#pragma unroll
        for (int j = 0; j < NK_; j++) {
            float ea = __shfl_sync(0xffffffffu, eA, selbase + j);
            float eb = __shfl_sync(0xffffffffu, eB, selbase + j);
            float wj = (g < 2) ? ea : eb;
            float2 lo = __half22float2(*(const __half2*)&f[j].x);
            float2 hi = __half22float2(*(const __half2*)&f[j].y);
            num.x = fmaf(wj, lo.x, num.x);
            num.y = fmaf(wj, lo.y, num.y);
            num.z = fmaf(wj, hi.x, num.z);
            num.w = fmaf(wj, hi.y, num.w);
            den += wj;
        }
        float inv = __fdividef(1.0f, den);
        float4 r = make_float4(num.x * inv, num.y * inv, num.z * inv, num.w * inv);
        ((float4*)(out + (size_t)bnk * D_))[sl] = r;
    } else {
        float4 s4 = ((const float4*)sigma)[sl];
        float c0 = 1.0f / (2.0f * s4.x * s4.x);
        float c1 = 1.0f / (2.0f * s4.y * s4.y);
        float c2 = 1.0f / (2.0f * s4.z * s4.z);
        float c3 = 1.0f / (2.0f * s4.w * s4.w);
        float d0 = 1e-9f, d1 = 1e-9f, d2 = 1e-9f, d3 = 1e-9f;
#pragma unroll
        for (int j = 0; j < NK_; j++) {
            float ta = __shfl_sync(0xffffffffu, tA, selbase + j);
            float tb = __shfl_sync(0xffffffffu, tB, selbase + j);
            float tv = (g < 2) ? ta : tb;
            float w0 = __expf(tv * c0);
            float w1 = __expf(tv * c1);
            float w2 = __expf(tv * c2);
            float w3 = __expf(tv * c3);
            float2 lo = __half22float2(*(const __half2*)&f[j].x);
            float2 hi = __half22float2(*(const __half2*)&f[j].y);
            num.x = fmaf(w0, lo.x, num.x);
            num.y = fmaf(w1, lo.y, num.y);
            num.z = fmaf(w2, hi.x, num.z);
            num.w = fmaf(w3, hi.y, num.w);
            d0 += w0; d1 += w1; d2 += w2; d3 += w3;
        }
        float4 r = make_float4(__fdividef(num.x, d0), __fdividef(num.y, d1),
                               __fdividef(num.z, d2), __fdividef(num.w, d3));
        ((float4*)(out + (size_t)bnk * D_))[sl] = r;
    }
}

// ---------- fused kernel: blocks [0, prep_blocks) do prep, rest do proj ----------
__global__ void __launch_bounds__(256, 6) fused_kernel(
    int prep_blocks, int prep_batch, int proj_batch,
    const float* __restrict__ x,
    const float* __restrict__ cin,
    const float* __restrict__ cout,
    const float* __restrict__ sigma,
    const int*   __restrict__ nidx,
    float* __restrict__ out)
{
    const int bid = (int)blockIdx.x;
    if (bid < prep_blocks) {
        prep_block(bid, prep_batch, x, sigma, cin);
    } else {
        proj_block(bid - prep_blocks, proj_batch, cout, sigma, nidx, out);
    }
}

extern "C" void kernel_launch(void* const* d_in, const int* in_sizes, int n_in,
                              void* d_out, int out_size) {
    const float* x     = (const float*)d_in[0];
    const float* cin   = (const float*)d_in[1];
    const float* cout  = (const float*)d_in[2];
    const float* sigma = (const float*)d_in[3];
    const int*   nidx  = (const int*)d_in[4];
    float* out = (float*)d_out;

    // K1: prep batch 0 only
    fused_kernel<<<PREP_BLOCKS_, 256>>>(PREP_BLOCKS_, 0, 0,
                                        x, cin, cout, sigma, nidx, out);
    // K2: prep batch 1 (first) + proj batch 0 — DRAM repack overlaps LTS gathers
    fused_kernel<<<PREP_BLOCKS_ + PROJ_BLOCKS_, 256>>>(PREP_BLOCKS_, 1, 0,
                                        x, cin, cout, sigma, nidx, out);
    // K3: proj batch 1 only
    fused_kernel<<<PROJ_BLOCKS_, 256>>>(0, 1, 1,
                                        x, cin, cout, sigma, nidx, out);
}